// round 11
// baseline (speedup 1.0000x reference)
#include <cuda_runtime.h>

// ---------------- constants ----------------
constexpr int Bq = 16, Nn = 1024, Tt = 12;
constexpr float EPS = 1e-5f;
constexpr float ISQ32 = 0.17677669529663689f; // 1/sqrt(32)

// ---------------- scratch (device globals; allocation is forbidden) ----------------
__device__ __align__(16) float g_TEmx[Bq * Tt * Nn];
__device__ __align__(16) float g_ctx [Bq * Tt * 96];
__device__ __align__(16) float g_TAT [Bq * Tt * Nn];
__device__ __align__(16) float g_SEmx[Bq * Nn * 512];
__device__ __align__(16) float g_Qs  [Bq * 3 * Nn * 32];
__device__ __align__(16) float g_Ks  [Bq * 3 * Nn * 32];
__device__ __align__(16) float g_rhs [Bq * 3 * Nn * Tt];
__device__ __align__(16) float g_tco [Bq * Nn * Tt * 32];
__device__ __align__(16) float g_am  [3 * Nn * Nn];
__device__ __align__(16) float g_xT  [Bq * Tt * Nn];
__device__ __align__(16) float g_qkvp[Bq * 32 * 288 * 12];
__device__ __align__(16) float g_X   [512 * 32 * 384];     // per-tile [c][r*12+t]

__device__ __forceinline__ float warpsum(float v) {
#pragma unroll
    for (int o = 16; o; o >>= 1) v += __shfl_xor_sync(0xffffffffu, v, o);
    return v;
}
__device__ __forceinline__ unsigned long long pack2(float lo, float hi) {
    unsigned long long r;
    asm("mov.b64 %0, {%1,%2};" : "=l"(r) : "f"(lo), "f"(hi));
    return r;
}
__device__ __forceinline__ void unpack2(unsigned long long v, float& lo, float& hi) {
    asm("mov.b64 {%0,%1}, %2;" : "=f"(lo), "=f"(hi) : "l"(v));
}
__device__ __forceinline__ void fma2(unsigned long long& d, unsigned long long a,
                                     unsigned long long b) {
    asm("fma.rn.f32x2 %0, %1, %2, %3;" : "=l"(d) : "l"(a), "l"(b), "l"(d));
}
__device__ __forceinline__ float tanh_ap(float x) {
    float y; asm("tanh.approx.f32 %0, %1;" : "=f"(y) : "f"(x)); return y;
}

// ============ K0: g_am[k,i,j] = adj[i,j] * mask[k,i,j] ============
__global__ void k0_am(const float* __restrict__ adj, const float* __restrict__ mask) {
    int i = blockIdx.x * 256 + threadIdx.x;          // over float4, total 786432
    const float4 a = ((const float4*)adj)[i & 0x3FFFF];
    const float4 m = ((const float4*)mask)[i];
    float4 r; r.x = a.x * m.x; r.y = a.y * m.y; r.z = a.z * m.z; r.w = a.w * m.w;
    ((float4*)g_am)[i] = r;
}

// ============ K0x: xT[b,t,n] = x[b,n,0,t] ============
__global__ void k0x_tr(const float* __restrict__ x) {
    __shared__ float sxt[128][13];
    int b = blockIdx.x >> 3, n0 = (blockIdx.x & 7) * 128;
    int tid = threadIdx.x;
    for (int i = tid; i < 384; i += 256) {
        int r = i / 3, q = i % 3;
        float4 f = *(const float4*)(x + ((b * Nn + n0 + r) * 12 + q * 4));
        sxt[r][q * 4] = f.x; sxt[r][q * 4 + 1] = f.y; sxt[r][q * 4 + 2] = f.z; sxt[r][q * 4 + 3] = f.w;
    }
    __syncthreads();
    for (int i = tid; i < 1536; i += 256) {
        int t = i >> 7, r = i & 127;
        g_xT[(b * 12 + t) * Nn + n0 + r] = sxt[r][t];
    }
}

// ============ K1: TEmx[b,t,n] = LN_n(xT[b,t,n] + peT[t,n]) * gT[n] + bT[n] ============
__global__ void k1_tln(const float* __restrict__ peT, const float* __restrict__ gT,
                       const float* __restrict__ bT) {
    int b = blockIdx.x / Tt, t = blockIdx.x % Tt;
    __shared__ float rb[20];
    int tid = threadIdx.x;
    float4 xv = *(const float4*)(g_xT + (b * 12 + t) * Nn + tid * 4);
    float4 pe = *(const float4*)(peT + t * Nn + tid * 4);
    float4 v; v.x = xv.x + pe.x; v.y = xv.y + pe.y; v.z = xv.z + pe.z; v.w = xv.w + pe.w;
    float s = v.x + v.y + v.z + v.w;
    float q = v.x * v.x + v.y * v.y + v.z * v.z + v.w * v.w;
    s = warpsum(s); q = warpsum(q);
    int w = tid >> 5, l = tid & 31;
    if (l == 0) { rb[w] = s; rb[w + 8] = q; }
    __syncthreads();
    if (tid == 0) {
        float S = 0.f, Q = 0.f;
        for (int i = 0; i < 8; i++) { S += rb[i]; Q += rb[i + 8]; }
        float mu = S * (1.f / Nn); float var = Q * (1.f / Nn) - mu * mu;
        rb[16] = mu; rb[17] = rsqrtf(var + EPS);
    }
    __syncthreads();
    float mu = rb[16], rs = rb[17];
    float4 g = *(const float4*)(gT + tid * 4);
    float4 be = *(const float4*)(bT + tid * 4);
    float4 o;
    o.x = (v.x - mu) * rs * g.x + be.x; o.y = (v.y - mu) * rs * g.y + be.y;
    o.z = (v.z - mu) * rs * g.z + be.z; o.w = (v.w - mu) * rs * g.w + be.w;
    *(float4*)(g_TEmx + (b * 12 + t) * Nn + tid * 4) = o;
}

// ============ K2a: partial QKV sums over 32-n chunks (grid 16*32) ============
__global__ void k2a_qkv(const float* __restrict__ WQ, const float* __restrict__ WK,
                        const float* __restrict__ WV) {
    int blk = blockIdx.x, b = blk >> 5, ch = blk & 31;
    int tid = threadIdx.x;                 // 288
    __shared__ float srow[12][32];
    float acc[12];
#pragma unroll
    for (int t = 0; t < 12; t++) acc[t] = 0.f;
    const float* W = (tid < 96) ? WQ : (tid < 192) ? WK : WV;
    int col = tid % 96;
    int n0 = ch * 32;
    if (tid < 288) {
        int t = tid >> 5, nn = tid & 31;
        if (t < 12) srow[t][nn] = g_TEmx[(b * 12 + t) * Nn + n0 + nn];
    }
    for (int i = tid + 288; i < 384; i += 288) {
        int t = i >> 5, nn = i & 31;
        srow[t][nn] = g_TEmx[(b * 12 + t) * Nn + n0 + nn];
    }
    __syncthreads();
    for (int nn = 0; nn < 32; nn++) {
        float w = W[(n0 + nn) * 96 + col];
#pragma unroll
        for (int t = 0; t < 12; t++) acc[t] += srow[t][nn] * w;
    }
    float* op = g_qkvp + ((size_t)blk * 288 + tid) * 12;
#pragma unroll
    for (int t = 0; t < 12; t++) op[t] = acc[t];
}

// ============ K2b: reduce partials + temporal MHA (writes re_At, ctx) ============
__global__ void k2b_attn(const float* __restrict__ resA, float* __restrict__ reOut) {
    int b = blockIdx.x, tid = threadIdx.x;   // 288 threads
    __shared__ float sM[3][3][12][33];
    __shared__ float sS[3][12][12];
    float acc[12];
#pragma unroll
    for (int t = 0; t < 12; t++) acc[t] = 0.f;
#pragma unroll 8
    for (int ch = 0; ch < 32; ch++) {
        const float4* pp = (const float4*)(g_qkvp + ((size_t)(b * 32 + ch) * 288 + tid) * 12);
        float4 p0 = pp[0], p1 = pp[1], p2 = pp[2];
        acc[0] += p0.x; acc[1] += p0.y; acc[2] += p0.z; acc[3] += p0.w;
        acc[4] += p1.x; acc[5] += p1.y; acc[6] += p1.z; acc[7] += p1.w;
        acc[8] += p2.x; acc[9] += p2.y; acc[10] += p2.z; acc[11] += p2.w;
    }
    int col = tid % 96;
    {
        int m = tid / 96, h = col >> 5, d = col & 31;
#pragma unroll
        for (int t = 0; t < 12; t++) sM[m][h][t][d] = acc[t];
    }
    __syncthreads();
    for (int i = tid; i < 432; i += 288) {
        int h = i / 144, rem = i % 144, q = rem / 12, kk = rem % 12;
        float s = 0.f;
#pragma unroll
        for (int d = 0; d < 32; d++) s += sM[0][h][q][d] * sM[1][h][kk][d];
        s = s * ISQ32 + resA[((b * 3 + h) * 12 + q) * 12 + kk];
        sS[h][q][kk] = s;
        reOut[((b * 3 + h) * 12 + q) * 12 + kk] = s;
    }
    __syncthreads();
    if (tid < 36) {
        int h = tid / 12, q = tid % 12;
        float mx = -1e30f;
        for (int kk = 0; kk < 12; kk++) mx = fmaxf(mx, sS[h][q][kk]);
        float e[12]; float sum = 0.f;
        for (int kk = 0; kk < 12; kk++) { e[kk] = __expf(sS[h][q][kk] - mx); sum += e[kk]; }
        float inv = 1.f / sum;
        for (int kk = 0; kk < 12; kk++) sS[h][q][kk] = e[kk] * inv;
    }
    __syncthreads();
    {
        int h = tid / 96, rem = tid % 96, d = rem & 31, qg = rem >> 5;
#pragma unroll
        for (int j = 0; j < 4; j++) {
            int q = qg * 4 + j;
            float s = 0.f;
#pragma unroll
            for (int kk = 0; kk < 12; kk++) s += sS[h][q][kk] * sM[2][h][kk][d];
            g_ctx[(b * 12 + q) * 96 + h * 32 + d] = s;
        }
    }
}

// ============ K3: TAT = LN_n(ctx @ fc_t + TEmx), gamma=1 beta=0 — float4 path ============
__global__ void k3_tat(const float* __restrict__ fct) {
    int b = blockIdx.x / 12, t = blockIdx.x % 12;
    __shared__ float sc[96];
    __shared__ float rb[20];
    int tid = threadIdx.x;
    if (tid < 96) sc[tid] = g_ctx[(b * 12 + t) * 96 + tid];
    __syncthreads();
    float4 a = *(const float4*)(g_TEmx + (b * 12 + t) * Nn + tid * 4);
    const float4* fp = (const float4*)fct;
#pragma unroll 4
    for (int j = 0; j < 96; j++) {
        float c = sc[j];
        float4 f = fp[j * 256 + tid];
        a.x += c * f.x; a.y += c * f.y; a.z += c * f.z; a.w += c * f.w;
    }
    float s = a.x + a.y + a.z + a.w;
    float q = a.x * a.x + a.y * a.y + a.z * a.z + a.w * a.w;
    s = warpsum(s); q = warpsum(q);
    int w = tid >> 5, l = tid & 31;
    if (l == 0) { rb[w] = s; rb[w + 8] = q; }
    __syncthreads();
    if (tid == 0) {
        float S = 0.f, Q = 0.f;
        for (int i = 0; i < 8; i++) { S += rb[i]; Q += rb[i + 8]; }
        float mu = S * (1.f / Nn); float var = Q * (1.f / Nn) - mu * mu;
        rb[16] = mu; rb[17] = rsqrtf(var + EPS);
    }
    __syncthreads();
    float mu = rb[16], rs = rb[17];
    float4 o;
    o.x = (a.x - mu) * rs; o.y = (a.y - mu) * rs; o.z = (a.z - mu) * rs; o.w = (a.w - mu) * rs;
    *(float4*)(g_TAT + (b * 12 + t) * Nn + tid * 4) = o;
}

// ============ K4: SEmx = LN_d(pre_conv(TAT) + peS) — 32-row tiles, weights in regs ============
constexpr int K4_SMEM = (32 * 512 + 32 * 13) * 4;   // sV + sTAT
__global__ __launch_bounds__(128, 3)
void k4_semx(const float* __restrict__ pcw, const float* __restrict__ pcb,
             const float* __restrict__ peS, const float* __restrict__ gS,
             const float* __restrict__ bS) {
    extern __shared__ float s4[];
    float* sV   = s4;            // [32][512]
    float* sTAT = s4 + 32 * 512; // [32][13]
    int tid = threadIdx.x;
    int row0 = blockIdx.x * 32;
    int b = row0 >> 10, n0 = row0 & 1023;
    int d0 = tid * 4;
    float w[12][4];
#pragma unroll
    for (int di = 0; di < 4; di++) {
        const float4* pw = (const float4*)(pcw + (d0 + di) * 12);
        float4 a = pw[0], bb = pw[1], c = pw[2];
        w[0][di] = a.x;  w[1][di] = a.y;  w[2][di] = a.z;  w[3][di] = a.w;
        w[4][di] = bb.x; w[5][di] = bb.y; w[6][di] = bb.z; w[7][di] = bb.w;
        w[8][di] = c.x;  w[9][di] = c.y;  w[10][di] = c.z; w[11][di] = c.w;
    }
    float4 bias = *(const float4*)(pcb + d0);
    for (int i = tid; i < 12 * 32; i += 128) {
        int t = i >> 5, r = i & 31;
        sTAT[r * 13 + t] = g_TAT[(b * 12 + t) * Nn + n0 + r];
    }
    __syncthreads();
    for (int r = 0; r < 32; r++) {
        float4 pe = *(const float4*)(peS + (n0 + r) * 512 + d0);
        float v0 = bias.x + pe.x, v1 = bias.y + pe.y, v2 = bias.z + pe.z, v3 = bias.w + pe.w;
#pragma unroll
        for (int t = 0; t < 12; t++) {
            float tv = sTAT[r * 13 + t];
            v0 += tv * w[t][0]; v1 += tv * w[t][1]; v2 += tv * w[t][2]; v3 += tv * w[t][3];
        }
        float4 vv; vv.x = v0; vv.y = v1; vv.z = v2; vv.w = v3;
        *(float4*)(sV + r * 512 + d0) = vv;
    }
    __syncthreads();
    int warp = tid >> 5, lane = tid & 31;
    float gsr[16], bsr[16];
#pragma unroll
    for (int i = 0; i < 16; i++) { gsr[i] = gS[lane + 32 * i]; bsr[i] = bS[lane + 32 * i]; }
    for (int r = warp; r < 32; r += 4) {
        float s = 0.f, q = 0.f; float v[16];
#pragma unroll
        for (int i = 0; i < 16; i++) {
            float a = sV[r * 512 + lane + 32 * i];
            v[i] = a; s += a; q += a * a;
        }
        s = warpsum(s); q = warpsum(q);
        float mu = s * (1.f / 512.f), var = q * (1.f / 512.f) - mu * mu, rs = rsqrtf(var + EPS);
        float* outp = g_SEmx + (size_t)(row0 + r) * 512;
#pragma unroll
        for (int i = 0; i < 16; i++)
            outp[lane + 32 * i] = (v[i] - mu) * rs * gsr[i] + bsr[i];
    }
}

// ============ K5: (16384,512) @ (512,192) -> Qs(pre-scaled)|Ks — f32x2 ============
__global__ void k5_qk(const float* __restrict__ WQs, const float* __restrict__ WKs) {
    __shared__ float sA[16 * 66];                 // stride 66 for 8B-aligned u64 loads
    __shared__ float sB2[16 * 6 * 33 * 2];        // [kk][v][tt] duplicated (b,b) u64
    int tid = threadIdx.x, tx = tid & 31, ty = tid >> 5;
    int m0 = blockIdx.x * 64;
    unsigned long long acc2[4][6];
#pragma unroll
    for (int u = 0; u < 4; u++)
#pragma unroll
        for (int v = 0; v < 6; v++) acc2[u][v] = pack2(0.f, 0.f);
    for (int k0 = 0; k0 < 512; k0 += 16) {
        __syncthreads();
        {
            int rowl = tid >> 2, kq = (tid & 3) * 4;
            const float4 f = *(const float4*)(g_SEmx + (size_t)(m0 + rowl) * 512 + k0 + kq);
            sA[kq * 66 + rowl] = f.x; sA[(kq + 1) * 66 + rowl] = f.y;
            sA[(kq + 2) * 66 + rowl] = f.z; sA[(kq + 3) * 66 + rowl] = f.w;
        }
        for (int i = tid; i < 16 * 192; i += 256) {
            int kk = i / 192, c = i % 192;
            float v = (c < 96) ? WQs[(k0 + kk) * 96 + c] : WKs[(k0 + kk) * 96 + c - 96];
            int idx = 2 * ((kk * 6 + (c % 6)) * 33 + (c / 6));
            sB2[idx] = v; sB2[idx + 1] = v;
        }
        __syncthreads();
#pragma unroll
        for (int kk = 0; kk < 16; kk++) {
            unsigned long long a2[4], b2[6];
#pragma unroll
            for (int u = 0; u < 4; u++)
                a2[u] = *(const unsigned long long*)(sA + kk * 66 + ty * 8 + 2 * u);
#pragma unroll
            for (int v = 0; v < 6; v++)
                b2[v] = *(const unsigned long long*)(sB2 + 2 * ((kk * 6 + v) * 33 + tx));
#pragma unroll
            for (int u = 0; u < 4; u++)
#pragma unroll
                for (int v = 0; v < 6; v++) fma2(acc2[u][v], a2[u], b2[v]);
        }
    }
    for (int u = 0; u < 4; u++)
        for (int v = 0; v < 6; v++) {
            float lo, hi; unpack2(acc2[u][v], lo, hi);
            int c = tx * 6 + v;
#pragma unroll
            for (int h = 0; h < 2; h++) {
                int m = m0 + ty * 8 + 2 * u + h;
                float val = h ? hi : lo;
                int b = m >> 10, n = m & 1023;
                if (c < 96) g_Qs[((b * 3 + (c >> 5)) * Nn + n) * 32 + (c & 31)] = val * ISQ32;
                else { int cc = c - 96; g_Ks[((b * 3 + (cc >> 5)) * Nn + n) * 32 + (cc & 31)] = val; }
            }
        }
}

// ============ K6: fused spatial scores + softmax(over i) + Cheb contraction — f32x2 ============
// R9-winning structure: 32-j tiles, separate g_am table + cheb via __restrict__ input pointer.
__global__ void k6_spatial(const float* __restrict__ cheb) {
    int bk = blockIdx.x >> 5, jt = blockIdx.x & 31;
    int b = bk / 3, k = bk % 3;
    int j0 = jt * 32;
    __shared__ float sK[32 * 34];
    __shared__ float sQ[64 * 34];
    __shared__ unsigned long long sS2[64 * 33];   // (w,w) duplicated
    __shared__ float2 sx2[64 * 6];
    __shared__ float sPart[8][33];
    __shared__ float sden[32];
    int tid = threadIdx.x;
    for (int i = tid; i < 1024; i += 256) {
        int j = i >> 5, d = i & 31;
        sK[j * 34 + d] = g_Ks[((b * 3 + k) * Nn + j0 + j) * 32 + d];
    }
    if (tid < 32) sden[tid] = 0.f;
    unsigned long long accAB = pack2(0.f, 0.f);
    int jj = tid & 31, tt = tid >> 5;   // accumulation mapping for tid<192
    int jS = tid & 31, rbk = tid >> 5;  // score mapping
    __syncthreads();
    for (int i0 = 0; i0 < Nn; i0 += 64) {
        for (int i = tid; i < 64 * 32; i += 256) {
            int r = i >> 5, d = i & 31;
            sQ[r * 34 + d] = g_Qs[((b * 3 + k) * Nn + i0 + r) * 32 + d];
        }
        for (int i = tid; i < 64 * 6; i += 256) {
            int tp = i >> 6, r = i & 63;
            sx2[r * 6 + tp] = make_float2(g_xT[(b * 12 + tp) * Nn + i0 + r],
                                          g_xT[(b * 12 + tp + 6) * Nn + i0 + r]);
        }
        __syncthreads();
        {   // scores (packed over d-pairs) + exp + cheb weighting
            unsigned long long a2[8];
#pragma unroll
            for (int r = 0; r < 8; r++) a2[r] = pack2(0.f, 0.f);
            const float* qb = sQ + (rbk * 8) * 34;
#pragma unroll
            for (int d2 = 0; d2 < 16; d2++) {
                unsigned long long kv = *(const unsigned long long*)(sK + jS * 34 + 2 * d2);
#pragma unroll
                for (int r = 0; r < 8; r++) {
                    unsigned long long qv = *(const unsigned long long*)(qb + r * 34 + 2 * d2);
                    fma2(a2[r], qv, kv);
                }
            }
            float ps = 0.f;
            int gj = j0 + jS;
#pragma unroll
            for (int r = 0; r < 8; r++) {
                float lo, hi; unpack2(a2[r], lo, hi);
                int gi = i0 + rbk * 8 + r;
                float e = __expf(lo + hi + g_am[(k * Nn + gi) * Nn + gj]);
                ps += e;
                float wcv = e * cheb[(k * Nn + gi) * Nn + gj];
                sS2[(rbk * 8 + r) * 33 + jS] = pack2(wcv, wcv);
            }
            sPart[rbk][jS] = ps;
        }
        __syncthreads();
        if (tid < 32) {
            float s2 = 0.f;
#pragma unroll
            for (int r = 0; r < 8; r++) s2 += sPart[r][tid];
            sden[tid] += s2;
        }
        if (tid < 192) {
#pragma unroll 4
            for (int i = 0; i < 64; i++) {
                unsigned long long wc2 = sS2[i * 33 + jj];
                unsigned long long x2 = *(const unsigned long long*)(sx2 + i * 6 + tt);
                fma2(accAB, wc2, x2);
            }
        }
        __syncthreads();
    }
    if (tid < 192) {
        float inv = 1.f / sden[jj];
        float a, bb; unpack2(accAB, a, bb);
        int base = ((b * 3 + k) * Nn + j0 + jj) * 12;
        g_rhs[base + tt]     = a * inv;
        g_rhs[base + tt + 6] = bb * inv;
    }
}

// ============ K7x: Theta-combine once per tile -> g_X[tile][c][r*12+t] ============
__global__ void k7x_theta(const float* __restrict__ th) {
    __shared__ float sR[1152];
    __shared__ float sTH[96];
    int tid = threadIdx.x;
    int rt0 = blockIdx.x * 32;
    if (tid < 96) sTH[tid] = th[tid];
    for (int i = tid; i < 1152; i += 256) {
        int k = i / 384, rem = i % 384;
        int row = rt0 + rem / 12;
        int b = row >> 10, n = row & 1023;
        sR[i] = g_rhs[((b * 3 + k) * Nn + n) * 12 + rem % 12];
    }
    __syncthreads();
    float* op = g_X + (size_t)blockIdx.x * 12288;
    for (int i = tid; i < 12288; i += 256) {
        int c = i / 384, rem = i % 384;
        float v = sR[rem] * sTH[c] + sR[384 + rem] * sTH[32 + c] + sR[768 + rem] * sTH[64 + c];
        op[i] = fmaxf(v, 0.f);
    }
}

// ============ K7a: GTU(3/5/7) + fcmy + inner relu -> g_tco (X from k7x) ============
constexpr int OFF_W = 0, OFF_X = 8256, OFF_FW = 20544, OFF_FB = 20832,
              K7_FLOATS = 20844;
__global__ __launch_bounds__(256, 2)
void k7a_gtu(const float* __restrict__ w3, const float* __restrict__ b3,
             const float* __restrict__ w5, const float* __restrict__ b5,
             const float* __restrict__ w7, const float* __restrict__ b7,
             const float* __restrict__ fw, const float* __restrict__ fb) {
    extern __shared__ float sm[];
    int tid = threadIdx.x;
    int og  = blockIdx.x & 3;
    for (int pi = tid; pi < 8 * 32 * 15; pi += 256) {
        int p = pi / 480, rem = pi % 480, c = rem / 15, j = rem % 15;
        int ot = og * 8 + p;
        float wt, ws;
        if (j < 3)      { wt = w3[(ot * 32 + c) * 3 + j];       ws = w3[((ot + 32) * 32 + c) * 3 + j]; }
        else if (j < 8) { wt = w5[(ot * 32 + c) * 5 + (j - 3)]; ws = w5[((ot + 32) * 32 + c) * 5 + (j - 3)]; }
        else            { wt = w7[(ot * 32 + c) * 7 + (j - 8)]; ws = w7[((ot + 32) * 32 + c) * 7 + (j - 8)]; }
        int off = OFF_W + p * 1032 + c * 32 + 2 * j;
        sm[off] = wt; sm[off + 1] = ws;
    }
    for (int pi = tid; pi < 144; pi += 256) {
        int j = pi / 6, tp = pi % 6;
        sm[OFF_FW + pi * 2]     = fw[j * 12 + tp];
        sm[OFF_FW + pi * 2 + 1] = fw[j * 12 + tp + 6];
    }
    if (tid < 6) { sm[OFF_FB + tid * 2] = fb[tid]; sm[OFF_FB + tid * 2 + 1] = fb[tid + 6]; }
    {   // stage X tile (coalesced float4 copy)
        const float4* src = (const float4*)(g_X + (size_t)(blockIdx.x >> 2) * 12288);
        float4* dst = (float4*)(sm + OFF_X);
        for (int i = tid; i < 3072; i += 256) dst[i] = src[i];
    }
    __syncthreads();
    int p = tid & 7, r = tid >> 3;
    unsigned long long A3[10], A5[8], A7[6];
    {
        int ot = og * 8 + p;
        unsigned long long v3 = pack2(b3[ot], b3[32 + ot]);
        unsigned long long v5 = pack2(b5[ot], b5[32 + ot]);
        unsigned long long v7 = pack2(b7[ot], b7[32 + ot]);
#pragma unroll
        for (int i = 0; i < 10; i++) A3[i] = v3;
#pragma unroll
        for (int i = 0; i < 8; i++)  A5[i] = v5;
#pragma unroll
        for (int i = 0; i < 6; i++)  A7[i] = v7;
    }
    const float* xb = sm + OFF_X + r * 12;
    const unsigned long long* wp =
        (const unsigned long long*)(sm + OFF_W + p * 1032);
    for (int c = 0; c < 32; c++) {
        float4 x0 = *(const float4*)(xb + c * 384);
        float4 x1 = *(const float4*)(xb + c * 384 + 4);
        float4 x2 = *(const float4*)(xb + c * 384 + 8);
        unsigned long long xp[12];
        xp[0] = pack2(x0.x, x0.x); xp[1] = pack2(x0.y, x0.y); xp[2] = pack2(x0.z, x0.z);
        xp[3] = pack2(x0.w, x0.w); xp[4] = pack2(x1.x, x1.x); xp[5] = pack2(x1.y, x1.y);
        xp[6] = pack2(x1.z, x1.z); xp[7] = pack2(x1.w, x1.w); xp[8] = pack2(x2.x, x2.x);
        xp[9] = pack2(x2.y, x2.y); xp[10] = pack2(x2.z, x2.z); xp[11] = pack2(x2.w, x2.w);
        const unsigned long long* wc = wp + c * 16;
        unsigned long long wv[15];
#pragma unroll
        for (int j = 0; j < 15; j++) wv[j] = wc[j];
#pragma unroll
        for (int j = 0; j < 3; j++)
#pragma unroll
            for (int t = 0; t < 10; t++) fma2(A3[t], wv[j], xp[t + j]);
#pragma unroll
        for (int j = 0; j < 5; j++)
#pragma unroll
            for (int t = 0; t < 8; t++) fma2(A5[t], wv[3 + j], xp[t + j]);
#pragma unroll
        for (int j = 0; j < 7; j++)
#pragma unroll
            for (int t = 0; t < 6; t++) fma2(A7[t], wv[8 + j], xp[t + j]);
    }
    unsigned long long g2[24];
#pragma unroll
    for (int t = 0; t < 10; t++) {
        float at, as; unpack2(A3[t], at, as);
        float g = tanh_ap(at) * __fdividef(1.f, 1.f + __expf(-as));
        g2[t] = pack2(g, g);
    }
#pragma unroll
    for (int t = 0; t < 8; t++) {
        float at, as; unpack2(A5[t], at, as);
        float g = tanh_ap(at) * __fdividef(1.f, 1.f + __expf(-as));
        g2[10 + t] = pack2(g, g);
    }
#pragma unroll
    for (int t = 0; t < 6; t++) {
        float at, as; unpack2(A7[t], at, as);
        float g = tanh_ap(at) * __fdividef(1.f, 1.f + __expf(-as));
        g2[18 + t] = pack2(g, g);
    }
    int row = (blockIdx.x >> 2) * 32 + r, oc = og * 8 + p;
    const unsigned long long* fwp = (const unsigned long long*)(sm + OFF_FW);
#pragma unroll
    for (int tp = 0; tp < 6; tp++) {
        unsigned long long acc = *(const unsigned long long*)(sm + OFF_FB + tp * 2);
#pragma unroll
        for (int j = 0; j < 24; j++) fma2(acc, g2[j], fwp[j * 6 + tp]);
        float lo, hi; unpack2(acc, lo, hi);
        g_tco[(row * 12 + tp) * 32 + oc]       = fmaxf(lo, 0.f);
        g_tco[(row * 12 + tp + 6) * 32 + oc]   = fmaxf(hi, 0.f);
    }
}

// ============ K7b: residual 1x1 conv + relu + channel LayerNorm -> out ============
__global__ void k7b_final(const float* __restrict__ xin, const float* __restrict__ rw,
                          const float* __restrict__ rb, const float* __restrict__ gf,
                          const float* __restrict__ bf, float* __restrict__ out) {
    __shared__ float sT[32 * 13];
    int bn = blockIdx.x;
    int t = threadIdx.x >> 5, c = threadIdx.x & 31;
    float xv = xin[bn * 12 + t];
    float v = fmaxf(xv * rw[c] + rb[c] + g_tco[(bn * 12 + t) * 32 + c], 0.f);
    float mu = warpsum(v) * (1.f / 32.f);
    float q  = warpsum(v * v) * (1.f / 32.f);
    float rs = rsqrtf(q - mu * mu + EPS);
    sT[c * 13 + t] = (v - mu) * rs * gf[c] + bf[c];
    __syncthreads();
    int cc = threadIdx.x / 12, tt2 = threadIdx.x % 12;
    out[bn * 384 + threadIdx.x] = sT[cc * 13 + tt2];
}

// ============================ launch ============================
extern "C" void kernel_launch(void* const* d_in, const int* in_sizes, int n_in,
                              void* d_out, int out_size) {
    const float* x    = (const float*)d_in[0];
    const float* resA = (const float*)d_in[1];
    const float* peT  = (const float*)d_in[2];
    const float* gT   = (const float*)d_in[3];
    const float* bT   = (const float*)d_in[4];
    const float* WQt  = (const float*)d_in[5];
    const float* WKt  = (const float*)d_in[6];
    const float* WVt  = (const float*)d_in[7];
    const float* fct  = (const float*)d_in[8];
    const float* pcw  = (const float*)d_in[9];
    const float* pcb  = (const float*)d_in[10];
    const float* peS  = (const float*)d_in[11];
    const float* gS   = (const float*)d_in[12];
    const float* bS   = (const float*)d_in[13];
    const float* WQs  = (const float*)d_in[14];
    const float* WKs  = (const float*)d_in[15];
    const float* cheb = (const float*)d_in[16];
    const float* adj  = (const float*)d_in[17];
    const float* mask = (const float*)d_in[18];
    const float* th   = (const float*)d_in[19];
    const float* w3   = (const float*)d_in[20];
    const float* b3   = (const float*)d_in[21];
    const float* w5   = (const float*)d_in[22];
    const float* b5   = (const float*)d_in[23];
    const float* w7   = (const float*)d_in[24];
    const float* b7   = (const float*)d_in[25];
    const float* rcw  = (const float*)d_in[26];
    const float* rcb  = (const float*)d_in[27];
    const float* fmw  = (const float*)d_in[28];
    const float* fmb  = (const float*)d_in[29];
    const float* gf   = (const float*)d_in[30];
    const float* bf   = (const float*)d_in[31];

    float* out   = (float*)d_out;
    float* reOut = out + (size_t)Bq * Nn * 32 * Tt;   // re_At follows main output

    cudaFuncSetAttribute(k7a_gtu, cudaFuncAttributeMaxDynamicSharedMemorySize, K7_FLOATS * 4);
    cudaFuncSetAttribute(k4_semx, cudaFuncAttributeMaxDynamicSharedMemorySize, K4_SMEM);

    k0_am    <<<3072, 256>>>(adj, mask);
    k0x_tr   <<<Bq * 8, 256>>>(x);
    k1_tln   <<<Bq * Tt, 256>>>(peT, gT, bT);
    k2a_qkv  <<<Bq * 32, 288>>>(WQt, WKt, WVt);
    k2b_attn <<<Bq, 288>>>(resA, reOut);
    k3_tat   <<<Bq * Tt, 256>>>(fct);
    k4_semx  <<<Bq * Nn / 32, 128, K4_SMEM>>>(pcw, pcb, peS, gS, bS);
    k5_qk    <<<Bq * Nn / 64, 256>>>(WQs, WKs);
    k6_spatial<<<Bq * 3 * 32, 256>>>(cheb);
    k7x_theta<<<Bq * Nn / 32, 256>>>(th);
    k7a_gtu  <<<(Bq * Nn / 32) * 4, 256, K7_FLOATS * 4>>>(w3, b3, w5, b5, w7, b7, fmw, fmb);
    k7b_final<<<Bq * Nn, 384>>>(x, rcw, rcb, gf, bf, out);
}

// round 12
// speedup vs baseline: 1.1105x; 1.1105x over previous
#include <cuda_runtime.h>

// ---------------- constants ----------------
constexpr int Bq = 16, Nn = 1024, Tt = 12;
constexpr float EPS = 1e-5f;
constexpr float ISQ32 = 0.17677669529663689f; // 1/sqrt(32)

// ---------------- scratch (device globals; allocation is forbidden) ----------------
__device__ __align__(16) float g_TEmx[Bq * Tt * Nn];
__device__ __align__(16) float g_ctx [Bq * Tt * 96];
__device__ __align__(16) float g_TAT [Bq * Tt * Nn];
__device__ __align__(16) float g_SEmx[Bq * Nn * 512];
__device__ __align__(16) float g_Qs  [Bq * 3 * Nn * 32];
__device__ __align__(16) float g_Ks  [Bq * 3 * Nn * 32];
__device__ __align__(16) float g_rhs [Bq * 3 * Nn * Tt];
__device__ __align__(16) float g_tco [Bq * Nn * Tt * 32];
__device__ __align__(16) float g_am  [3 * Nn * Nn];
__device__ __align__(16) float g_xT  [Bq * Tt * Nn];
__device__ __align__(16) float g_qkvp[Bq * 32 * 288 * 12];

__device__ __forceinline__ float warpsum(float v) {
#pragma unroll
    for (int o = 16; o; o >>= 1) v += __shfl_xor_sync(0xffffffffu, v, o);
    return v;
}
__device__ __forceinline__ unsigned long long pack2(float lo, float hi) {
    unsigned long long r;
    asm("mov.b64 %0, {%1,%2};" : "=l"(r) : "f"(lo), "f"(hi));
    return r;
}
__device__ __forceinline__ void unpack2(unsigned long long v, float& lo, float& hi) {
    asm("mov.b64 {%0,%1}, %2;" : "=f"(lo), "=f"(hi) : "l"(v));
}
__device__ __forceinline__ void fma2(unsigned long long& d, unsigned long long a,
                                     unsigned long long b) {
    asm("fma.rn.f32x2 %0, %1, %2, %3;" : "=l"(d) : "l"(a), "l"(b), "l"(d));
}
__device__ __forceinline__ float tanh_ap(float x) {
    float y; asm("tanh.approx.f32 %0, %1;" : "=f"(y) : "f"(x)); return y;
}

// ============ K0: g_am[k,i,j] = adj[i,j] * mask[k,i,j] ============
__global__ void k0_am(const float* __restrict__ adj, const float* __restrict__ mask) {
    int i = blockIdx.x * 256 + threadIdx.x;          // over float4, total 786432
    const float4 a = ((const float4*)adj)[i & 0x3FFFF];
    const float4 m = ((const float4*)mask)[i];
    float4 r; r.x = a.x * m.x; r.y = a.y * m.y; r.z = a.z * m.z; r.w = a.w * m.w;
    ((float4*)g_am)[i] = r;
}

// ============ K0x: xT[b,t,n] = x[b,n,0,t] ============
__global__ void k0x_tr(const float* __restrict__ x) {
    __shared__ float sxt[128][13];
    int b = blockIdx.x >> 3, n0 = (blockIdx.x & 7) * 128;
    int tid = threadIdx.x;
    for (int i = tid; i < 384; i += 256) {
        int r = i / 3, q = i % 3;
        float4 f = *(const float4*)(x + ((b * Nn + n0 + r) * 12 + q * 4));
        sxt[r][q * 4] = f.x; sxt[r][q * 4 + 1] = f.y; sxt[r][q * 4 + 2] = f.z; sxt[r][q * 4 + 3] = f.w;
    }
    __syncthreads();
    for (int i = tid; i < 1536; i += 256) {
        int t = i >> 7, r = i & 127;
        g_xT[(b * 12 + t) * Nn + n0 + r] = sxt[r][t];
    }
}

// ============ K1: TEmx[b,t,n] = LN_n(xT[b,t,n] + peT[t,n]) * gT[n] + bT[n] ============
__global__ void k1_tln(const float* __restrict__ peT, const float* __restrict__ gT,
                       const float* __restrict__ bT) {
    int b = blockIdx.x / Tt, t = blockIdx.x % Tt;
    __shared__ float rb[20];
    int tid = threadIdx.x;
    float4 xv = *(const float4*)(g_xT + (b * 12 + t) * Nn + tid * 4);
    float4 pe = *(const float4*)(peT + t * Nn + tid * 4);
    float4 v; v.x = xv.x + pe.x; v.y = xv.y + pe.y; v.z = xv.z + pe.z; v.w = xv.w + pe.w;
    float s = v.x + v.y + v.z + v.w;
    float q = v.x * v.x + v.y * v.y + v.z * v.z + v.w * v.w;
    s = warpsum(s); q = warpsum(q);
    int w = tid >> 5, l = tid & 31;
    if (l == 0) { rb[w] = s; rb[w + 8] = q; }
    __syncthreads();
    if (tid == 0) {
        float S = 0.f, Q = 0.f;
        for (int i = 0; i < 8; i++) { S += rb[i]; Q += rb[i + 8]; }
        float mu = S * (1.f / Nn); float var = Q * (1.f / Nn) - mu * mu;
        rb[16] = mu; rb[17] = rsqrtf(var + EPS);
    }
    __syncthreads();
    float mu = rb[16], rs = rb[17];
    float4 g = *(const float4*)(gT + tid * 4);
    float4 be = *(const float4*)(bT + tid * 4);
    float4 o;
    o.x = (v.x - mu) * rs * g.x + be.x; o.y = (v.y - mu) * rs * g.y + be.y;
    o.z = (v.z - mu) * rs * g.z + be.z; o.w = (v.w - mu) * rs * g.w + be.w;
    *(float4*)(g_TEmx + (b * 12 + t) * Nn + tid * 4) = o;
}

// ============ K2a: partial QKV sums over 32-n chunks (grid 16*32) ============
__global__ void k2a_qkv(const float* __restrict__ WQ, const float* __restrict__ WK,
                        const float* __restrict__ WV) {
    int blk = blockIdx.x, b = blk >> 5, ch = blk & 31;
    int tid = threadIdx.x;                 // 288
    __shared__ float srow[12][32];
    float acc[12];
#pragma unroll
    for (int t = 0; t < 12; t++) acc[t] = 0.f;
    const float* W = (tid < 96) ? WQ : (tid < 192) ? WK : WV;
    int col = tid % 96;
    int n0 = ch * 32;
    if (tid < 288) {
        int t = tid >> 5, nn = tid & 31;
        if (t < 12) srow[t][nn] = g_TEmx[(b * 12 + t) * Nn + n0 + nn];
    }
    for (int i = tid + 288; i < 384; i += 288) {
        int t = i >> 5, nn = i & 31;
        srow[t][nn] = g_TEmx[(b * 12 + t) * Nn + n0 + nn];
    }
    __syncthreads();
    for (int nn = 0; nn < 32; nn++) {
        float w = W[(n0 + nn) * 96 + col];
#pragma unroll
        for (int t = 0; t < 12; t++) acc[t] += srow[t][nn] * w;
    }
    float* op = g_qkvp + ((size_t)blk * 288 + tid) * 12;
#pragma unroll
    for (int t = 0; t < 12; t++) op[t] = acc[t];
}

// ============ K2b: reduce partials + temporal MHA (writes re_At, ctx) ============
__global__ void k2b_attn(const float* __restrict__ resA, float* __restrict__ reOut) {
    int b = blockIdx.x, tid = threadIdx.x;   // 288 threads
    __shared__ float sM[3][3][12][33];
    __shared__ float sS[3][12][12];
    float acc[12];
#pragma unroll
    for (int t = 0; t < 12; t++) acc[t] = 0.f;
#pragma unroll 8
    for (int ch = 0; ch < 32; ch++) {
        const float4* pp = (const float4*)(g_qkvp + ((size_t)(b * 32 + ch) * 288 + tid) * 12);
        float4 p0 = pp[0], p1 = pp[1], p2 = pp[2];
        acc[0] += p0.x; acc[1] += p0.y; acc[2] += p0.z; acc[3] += p0.w;
        acc[4] += p1.x; acc[5] += p1.y; acc[6] += p1.z; acc[7] += p1.w;
        acc[8] += p2.x; acc[9] += p2.y; acc[10] += p2.z; acc[11] += p2.w;
    }
    int col = tid % 96;
    {
        int m = tid / 96, h = col >> 5, d = col & 31;
#pragma unroll
        for (int t = 0; t < 12; t++) sM[m][h][t][d] = acc[t];
    }
    __syncthreads();
    for (int i = tid; i < 432; i += 288) {
        int h = i / 144, rem = i % 144, q = rem / 12, kk = rem % 12;
        float s = 0.f;
#pragma unroll
        for (int d = 0; d < 32; d++) s += sM[0][h][q][d] * sM[1][h][kk][d];
        s = s * ISQ32 + resA[((b * 3 + h) * 12 + q) * 12 + kk];
        sS[h][q][kk] = s;
        reOut[((b * 3 + h) * 12 + q) * 12 + kk] = s;
    }
    __syncthreads();
    if (tid < 36) {
        int h = tid / 12, q = tid % 12;
        float mx = -1e30f;
        for (int kk = 0; kk < 12; kk++) mx = fmaxf(mx, sS[h][q][kk]);
        float e[12]; float sum = 0.f;
        for (int kk = 0; kk < 12; kk++) { e[kk] = __expf(sS[h][q][kk] - mx); sum += e[kk]; }
        float inv = 1.f / sum;
        for (int kk = 0; kk < 12; kk++) sS[h][q][kk] = e[kk] * inv;
    }
    __syncthreads();
    {
        int h = tid / 96, rem = tid % 96, d = rem & 31, qg = rem >> 5;
#pragma unroll
        for (int j = 0; j < 4; j++) {
            int q = qg * 4 + j;
            float s = 0.f;
#pragma unroll
            for (int kk = 0; kk < 12; kk++) s += sS[h][q][kk] * sM[2][h][kk][d];
            g_ctx[(b * 12 + q) * 96 + h * 32 + d] = s;
        }
    }
}

// ============ K3: TAT = LN_n(ctx @ fc_t + TEmx), gamma=1 beta=0 — float4 path ============
__global__ void k3_tat(const float* __restrict__ fct) {
    int b = blockIdx.x / 12, t = blockIdx.x % 12;
    __shared__ float sc[96];
    __shared__ float rb[20];
    int tid = threadIdx.x;
    if (tid < 96) sc[tid] = g_ctx[(b * 12 + t) * 96 + tid];
    __syncthreads();
    float4 a = *(const float4*)(g_TEmx + (b * 12 + t) * Nn + tid * 4);
    const float4* fp = (const float4*)fct;
#pragma unroll 4
    for (int j = 0; j < 96; j++) {
        float c = sc[j];
        float4 f = fp[j * 256 + tid];
        a.x += c * f.x; a.y += c * f.y; a.z += c * f.z; a.w += c * f.w;
    }
    float s = a.x + a.y + a.z + a.w;
    float q = a.x * a.x + a.y * a.y + a.z * a.z + a.w * a.w;
    s = warpsum(s); q = warpsum(q);
    int w = tid >> 5, l = tid & 31;
    if (l == 0) { rb[w] = s; rb[w + 8] = q; }
    __syncthreads();
    if (tid == 0) {
        float S = 0.f, Q = 0.f;
        for (int i = 0; i < 8; i++) { S += rb[i]; Q += rb[i + 8]; }
        float mu = S * (1.f / Nn); float var = Q * (1.f / Nn) - mu * mu;
        rb[16] = mu; rb[17] = rsqrtf(var + EPS);
    }
    __syncthreads();
    float mu = rb[16], rs = rb[17];
    float4 o;
    o.x = (a.x - mu) * rs; o.y = (a.y - mu) * rs; o.z = (a.z - mu) * rs; o.w = (a.w - mu) * rs;
    *(float4*)(g_TAT + (b * 12 + t) * Nn + tid * 4) = o;
}

// ============ K4: SEmx = LN_d(pre_conv(TAT) + peS) — 32-row tiles, weights in regs ============
constexpr int K4_SMEM = (32 * 512 + 32 * 13) * 4;   // sV + sTAT
__global__ __launch_bounds__(128, 3)
void k4_semx(const float* __restrict__ pcw, const float* __restrict__ pcb,
             const float* __restrict__ peS, const float* __restrict__ gS,
             const float* __restrict__ bS) {
    extern __shared__ float s4[];
    float* sV   = s4;            // [32][512]
    float* sTAT = s4 + 32 * 512; // [32][13]
    int tid = threadIdx.x;
    int row0 = blockIdx.x * 32;
    int b = row0 >> 10, n0 = row0 & 1023;
    int d0 = tid * 4;
    float w[12][4];
#pragma unroll
    for (int di = 0; di < 4; di++) {
        const float4* pw = (const float4*)(pcw + (d0 + di) * 12);
        float4 a = pw[0], bb = pw[1], c = pw[2];
        w[0][di] = a.x;  w[1][di] = a.y;  w[2][di] = a.z;  w[3][di] = a.w;
        w[4][di] = bb.x; w[5][di] = bb.y; w[6][di] = bb.z; w[7][di] = bb.w;
        w[8][di] = c.x;  w[9][di] = c.y;  w[10][di] = c.z; w[11][di] = c.w;
    }
    float4 bias = *(const float4*)(pcb + d0);
    for (int i = tid; i < 12 * 32; i += 128) {
        int t = i >> 5, r = i & 31;
        sTAT[r * 13 + t] = g_TAT[(b * 12 + t) * Nn + n0 + r];
    }
    __syncthreads();
    for (int r = 0; r < 32; r++) {
        float4 pe = *(const float4*)(peS + (n0 + r) * 512 + d0);
        float v0 = bias.x + pe.x, v1 = bias.y + pe.y, v2 = bias.z + pe.z, v3 = bias.w + pe.w;
#pragma unroll
        for (int t = 0; t < 12; t++) {
            float tv = sTAT[r * 13 + t];
            v0 += tv * w[t][0]; v1 += tv * w[t][1]; v2 += tv * w[t][2]; v3 += tv * w[t][3];
        }
        float4 vv; vv.x = v0; vv.y = v1; vv.z = v2; vv.w = v3;
        *(float4*)(sV + r * 512 + d0) = vv;
    }
    __syncthreads();
    int warp = tid >> 5, lane = tid & 31;
    float gsr[16], bsr[16];
#pragma unroll
    for (int i = 0; i < 16; i++) { gsr[i] = gS[lane + 32 * i]; bsr[i] = bS[lane + 32 * i]; }
    for (int r = warp; r < 32; r += 4) {
        float s = 0.f, q = 0.f; float v[16];
#pragma unroll
        for (int i = 0; i < 16; i++) {
            float a = sV[r * 512 + lane + 32 * i];
            v[i] = a; s += a; q += a * a;
        }
        s = warpsum(s); q = warpsum(q);
        float mu = s * (1.f / 512.f), var = q * (1.f / 512.f) - mu * mu, rs = rsqrtf(var + EPS);
        float* outp = g_SEmx + (size_t)(row0 + r) * 512;
#pragma unroll
        for (int i = 0; i < 16; i++)
            outp[lane + 32 * i] = (v[i] - mu) * rs * gsr[i] + bsr[i];
    }
}

// ============ K5: (16384,512) @ (512,192) -> Qs(pre-scaled)|Ks — f32x2 ============
__global__ void k5_qk(const float* __restrict__ WQs, const float* __restrict__ WKs) {
    __shared__ float sA[16 * 66];                 // stride 66 for 8B-aligned u64 loads
    __shared__ float sB2[16 * 6 * 33 * 2];        // [kk][v][tt] duplicated (b,b) u64
    int tid = threadIdx.x, tx = tid & 31, ty = tid >> 5;
    int m0 = blockIdx.x * 64;
    unsigned long long acc2[4][6];
#pragma unroll
    for (int u = 0; u < 4; u++)
#pragma unroll
        for (int v = 0; v < 6; v++) acc2[u][v] = pack2(0.f, 0.f);
    for (int k0 = 0; k0 < 512; k0 += 16) {
        __syncthreads();
        {
            int rowl = tid >> 2, kq = (tid & 3) * 4;
            const float4 f = *(const float4*)(g_SEmx + (size_t)(m0 + rowl) * 512 + k0 + kq);
            sA[kq * 66 + rowl] = f.x; sA[(kq + 1) * 66 + rowl] = f.y;
            sA[(kq + 2) * 66 + rowl] = f.z; sA[(kq + 3) * 66 + rowl] = f.w;
        }
        for (int i = tid; i < 16 * 192; i += 256) {
            int kk = i / 192, c = i % 192;
            float v = (c < 96) ? WQs[(k0 + kk) * 96 + c] : WKs[(k0 + kk) * 96 + c - 96];
            int idx = 2 * ((kk * 6 + (c % 6)) * 33 + (c / 6));
            sB2[idx] = v; sB2[idx + 1] = v;
        }
        __syncthreads();
#pragma unroll
        for (int kk = 0; kk < 16; kk++) {
            unsigned long long a2[4], b2[6];
#pragma unroll
            for (int u = 0; u < 4; u++)
                a2[u] = *(const unsigned long long*)(sA + kk * 66 + ty * 8 + 2 * u);
#pragma unroll
            for (int v = 0; v < 6; v++)
                b2[v] = *(const unsigned long long*)(sB2 + 2 * ((kk * 6 + v) * 33 + tx));
#pragma unroll
            for (int u = 0; u < 4; u++)
#pragma unroll
                for (int v = 0; v < 6; v++) fma2(acc2[u][v], a2[u], b2[v]);
        }
    }
    for (int u = 0; u < 4; u++)
        for (int v = 0; v < 6; v++) {
            float lo, hi; unpack2(acc2[u][v], lo, hi);
            int c = tx * 6 + v;
#pragma unroll
            for (int h = 0; h < 2; h++) {
                int m = m0 + ty * 8 + 2 * u + h;
                float val = h ? hi : lo;
                int b = m >> 10, n = m & 1023;
                if (c < 96) g_Qs[((b * 3 + (c >> 5)) * Nn + n) * 32 + (c & 31)] = val * ISQ32;
                else { int cc = c - 96; g_Ks[((b * 3 + (cc >> 5)) * Nn + n) * 32 + (cc & 31)] = val; }
            }
        }
}

// ============ K6: fused spatial scores + softmax(over i) + Cheb contraction — f32x2 ============
// Scorer-side accumulation: thread (jS, rbk) scores its 8 rows AND accumulates its
// partial rhs[jS, 0..11] + denominator over those rows. One cross-rbk reduction at end.
__global__ void k6_spatial(const float* __restrict__ cheb) {
    int bk = blockIdx.x >> 5, jt = blockIdx.x & 31;
    int b = bk / 3, k = bk % 3;
    int j0 = jt * 32;
    __shared__ float sK[32 * 34];
    __shared__ float sQ[64 * 34];
    __shared__ float2 sx2[64 * 6];
    __shared__ float sRed[8 * 32 * 14];   // [rbk][j][14]: 12 acc + den (+pad)
    int tid = threadIdx.x;
    int jS = tid & 31, rbk = tid >> 5;
    for (int i = tid; i < 1024; i += 256) {
        int j = i >> 5, d = i & 31;
        sK[j * 34 + d] = g_Ks[((b * 3 + k) * Nn + j0 + j) * 32 + d];
    }
    unsigned long long acc[6];
#pragma unroll
    for (int tp = 0; tp < 6; tp++) acc[tp] = pack2(0.f, 0.f);
    float den = 0.f;
    int gj = j0 + jS;
    __syncthreads();
    for (int i0 = 0; i0 < Nn; i0 += 64) {
        for (int i = tid; i < 64 * 32; i += 256) {
            int r = i >> 5, d = i & 31;
            sQ[r * 34 + d] = g_Qs[((b * 3 + k) * Nn + i0 + r) * 32 + d];
        }
        for (int i = tid; i < 64 * 6; i += 256) {
            int tp = i >> 6, r = i & 63;
            sx2[r * 6 + tp] = make_float2(g_xT[(b * 12 + tp) * Nn + i0 + r],
                                          g_xT[(b * 12 + tp + 6) * Nn + i0 + r]);
        }
        __syncthreads();
        {   // scores (packed over d-pairs)
            unsigned long long a2[8];
#pragma unroll
            for (int r = 0; r < 8; r++) a2[r] = pack2(0.f, 0.f);
            const float* qb = sQ + (rbk * 8) * 34;
#pragma unroll
            for (int d2 = 0; d2 < 16; d2++) {
                unsigned long long kv = *(const unsigned long long*)(sK + jS * 34 + 2 * d2);
#pragma unroll
                for (int r = 0; r < 8; r++) {
                    unsigned long long qv = *(const unsigned long long*)(qb + r * 34 + 2 * d2);
                    fma2(a2[r], qv, kv);
                }
            }
            // exp + cheb weight + direct accumulation over this thread's 8 rows
#pragma unroll
            for (int r = 0; r < 8; r++) {
                float lo, hi; unpack2(a2[r], lo, hi);
                int gi = i0 + rbk * 8 + r;
                float e = __expf(lo + hi + g_am[(k * Nn + gi) * Nn + gj]);
                den += e;
                float wcv = e * cheb[(k * Nn + gi) * Nn + gj];
                unsigned long long w2 = pack2(wcv, wcv);
                const unsigned long long* xp =
                    (const unsigned long long*)(sx2 + (rbk * 8 + r) * 6);
#pragma unroll
                for (int tp = 0; tp < 6; tp++) fma2(acc[tp], w2, xp[tp]);
            }
        }
        __syncthreads();
    }
    // cross-rbk reduction (once per block)
    {
        float* row = sRed + (rbk * 32 + jS) * 14;
#pragma unroll
        for (int tp = 0; tp < 6; tp++) {
            float lo, hi; unpack2(acc[tp], lo, hi);
            row[tp] = lo; row[tp + 6] = hi;
        }
        row[12] = den;
    }
    __syncthreads();
    for (int idx = tid; idx < 384; idx += 256) {
        int t = idx >> 5, j = idx & 31;
        float s = 0.f, d2 = 0.f;
#pragma unroll
        for (int g = 0; g < 8; g++) {
            const float* row = sRed + (g * 32 + j) * 14;
            s += row[t]; d2 += row[12];
        }
        g_rhs[((b * 3 + k) * Nn + j0 + j) * 12 + t] = s / d2;
    }
}

// ============ K7a: Theta-combine + GTU(3/5/7) + fcmy + inner relu -> g_tco ============
constexpr int OFF_W = 0, OFF_X = 8256, OFF_R = 20544, OFF_FW = 21696,
              OFF_TH = 21984, OFF_FB = 22080, K7_FLOATS = 22092;
__global__ __launch_bounds__(256, 2)
void k7a_gtu(const float* __restrict__ th,
             const float* __restrict__ w3, const float* __restrict__ b3,
             const float* __restrict__ w5, const float* __restrict__ b5,
             const float* __restrict__ w7, const float* __restrict__ b7,
             const float* __restrict__ fw, const float* __restrict__ fb) {
    extern __shared__ float sm[];
    int tid = threadIdx.x;
    int og  = blockIdx.x & 3;
    int rt0 = (blockIdx.x >> 2) * 32;
    for (int pi = tid; pi < 8 * 32 * 15; pi += 256) {
        int p = pi / 480, rem = pi % 480, c = rem / 15, j = rem % 15;
        int ot = og * 8 + p;
        float wt, ws;
        if (j < 3)      { wt = w3[(ot * 32 + c) * 3 + j];       ws = w3[((ot + 32) * 32 + c) * 3 + j]; }
        else if (j < 8) { wt = w5[(ot * 32 + c) * 5 + (j - 3)]; ws = w5[((ot + 32) * 32 + c) * 5 + (j - 3)]; }
        else            { wt = w7[(ot * 32 + c) * 7 + (j - 8)]; ws = w7[((ot + 32) * 32 + c) * 7 + (j - 8)]; }
        int off = OFF_W + p * 1032 + c * 32 + 2 * j;
        sm[off] = wt; sm[off + 1] = ws;
    }
    for (int pi = tid; pi < 144; pi += 256) {
        int j = pi / 6, tp = pi % 6;
        sm[OFF_FW + pi * 2]     = fw[j * 12 + tp];
        sm[OFF_FW + pi * 2 + 1] = fw[j * 12 + tp + 6];
    }
    if (tid < 96) sm[OFF_TH + tid] = th[tid];
    if (tid < 6) { sm[OFF_FB + tid * 2] = fb[tid]; sm[OFF_FB + tid * 2 + 1] = fb[tid + 6]; }
    for (int i = tid; i < 1152; i += 256) {
        int k = i / 384, rem = i % 384;
        int row = rt0 + rem / 12;
        int b = row >> 10, n = row & 1023;
        sm[OFF_R + i] = g_rhs[((b * 3 + k) * Nn + n) * 12 + rem % 12];
    }
    __syncthreads();
    for (int i = tid; i < 12288; i += 256) {
        int c = i / 384, rem = i % 384;
        float v = sm[OFF_R + rem] * sm[OFF_TH + c] + sm[OFF_R + 384 + rem] * sm[OFF_TH + 32 + c]
                + sm[OFF_R + 768 + rem] * sm[OFF_TH + 64 + c];
        sm[OFF_X + i] = fmaxf(v, 0.f);
    }
    __syncthreads();
    int p = tid & 7, r = tid >> 3;
    unsigned long long A3[10], A5[8], A7[6];
    {
        int ot = og * 8 + p;
        unsigned long long v3 = pack2(b3[ot], b3[32 + ot]);
        unsigned long long v5 = pack2(b5[ot], b5[32 + ot]);
        unsigned long long v7 = pack2(b7[ot], b7[32 + ot]);
#pragma unroll
        for (int i = 0; i < 10; i++) A3[i] = v3;
#pragma unroll
        for (int i = 0; i < 8; i++)  A5[i] = v5;
#pragma unroll
        for (int i = 0; i < 6; i++)  A7[i] = v7;
    }
    const float* xb = sm + OFF_X + r * 12;
    const unsigned long long* wp =
        (const unsigned long long*)(sm + OFF_W + p * 1032);
    for (int c = 0; c < 32; c++) {
        float4 x0 = *(const float4*)(xb + c * 384);
        float4 x1 = *(const float4*)(xb + c * 384 + 4);
        float4 x2 = *(const float4*)(xb + c * 384 + 8);
        unsigned long long xp[12];
        xp[0] = pack2(x0.x, x0.x); xp[1] = pack2(x0.y, x0.y); xp[2] = pack2(x0.z, x0.z);
        xp[3] = pack2(x0.w, x0.w); xp[4] = pack2(x1.x, x1.x); xp[5] = pack2(x1.y, x1.y);
        xp[6] = pack2(x1.z, x1.z); xp[7] = pack2(x1.w, x1.w); xp[8] = pack2(x2.x, x2.x);
        xp[9] = pack2(x2.y, x2.y); xp[10] = pack2(x2.z, x2.z); xp[11] = pack2(x2.w, x2.w);
        const unsigned long long* wc = wp + c * 16;
        unsigned long long wv[15];
#pragma unroll
        for (int j = 0; j < 15; j++) wv[j] = wc[j];
#pragma unroll
        for (int j = 0; j < 3; j++)
#pragma unroll
            for (int t = 0; t < 10; t++) fma2(A3[t], wv[j], xp[t + j]);
#pragma unroll
        for (int j = 0; j < 5; j++)
#pragma unroll
            for (int t = 0; t < 8; t++) fma2(A5[t], wv[3 + j], xp[t + j]);
#pragma unroll
        for (int j = 0; j < 7; j++)
#pragma unroll
            for (int t = 0; t < 6; t++) fma2(A7[t], wv[8 + j], xp[t + j]);
    }
    unsigned long long g2[24];
#pragma unroll
    for (int t = 0; t < 10; t++) {
        float at, as; unpack2(A3[t], at, as);
        float g = tanh_ap(at) * __fdividef(1.f, 1.f + __expf(-as));
        g2[t] = pack2(g, g);
    }
#pragma unroll
    for (int t = 0; t < 8; t++) {
        float at, as; unpack2(A5[t], at, as);
        float g = tanh_ap(at) * __fdividef(1.f, 1.f + __expf(-as));
        g2[10 + t] = pack2(g, g);
    }
#pragma unroll
    for (int t = 0; t < 6; t++) {
        float at, as; unpack2(A7[t], at, as);
        float g = tanh_ap(at) * __fdividef(1.f, 1.f + __expf(-as));
        g2[18 + t] = pack2(g, g);
    }
    int row = rt0 + r, oc = og * 8 + p;
    const unsigned long long* fwp = (const unsigned long long*)(sm + OFF_FW);
#pragma unroll
    for (int tp = 0; tp < 6; tp++) {
        unsigned long long acc = *(const unsigned long long*)(sm + OFF_FB + tp * 2);
#pragma unroll
        for (int j = 0; j < 24; j++) fma2(acc, g2[j], fwp[j * 6 + tp]);
        float lo, hi; unpack2(acc, lo, hi);
        g_tco[(row * 12 + tp) * 32 + oc]       = fmaxf(lo, 0.f);
        g_tco[(row * 12 + tp + 6) * 32 + oc]   = fmaxf(hi, 0.f);
    }
}

// ============ K7b: residual 1x1 conv + relu + channel LayerNorm -> out ============
__global__ void k7b_final(const float* __restrict__ xin, const float* __restrict__ rw,
                          const float* __restrict__ rb, const float* __restrict__ gf,
                          const float* __restrict__ bf, float* __restrict__ out) {
    __shared__ float sT[32 * 13];
    int bn = blockIdx.x;
    int t = threadIdx.x >> 5, c = threadIdx.x & 31;
    float xv = xin[bn * 12 + t];
    float v = fmaxf(xv * rw[c] + rb[c] + g_tco[(bn * 12 + t) * 32 + c], 0.f);
    float mu = warpsum(v) * (1.f / 32.f);
    float q  = warpsum(v * v) * (1.f / 32.f);
    float rs = rsqrtf(q - mu * mu + EPS);
    sT[c * 13 + t] = (v - mu) * rs * gf[c] + bf[c];
    __syncthreads();
    int cc = threadIdx.x / 12, tt2 = threadIdx.x % 12;
    out[bn * 384 + threadIdx.x] = sT[cc * 13 + tt2];
}

// ============================ launch ============================
extern "C" void kernel_launch(void* const* d_in, const int* in_sizes, int n_in,
                              void* d_out, int out_size) {
    const float* x    = (const float*)d_in[0];
    const float* resA = (const float*)d_in[1];
    const float* peT  = (const float*)d_in[2];
    const float* gT   = (const float*)d_in[3];
    const float* bT   = (const float*)d_in[4];
    const float* WQt  = (const float*)d_in[5];
    const float* WKt  = (const float*)d_in[6];
    const float* WVt  = (const float*)d_in[7];
    const float* fct  = (const float*)d_in[8];
    const float* pcw  = (const float*)d_in[9];
    const float* pcb  = (const float*)d_in[10];
    const float* peS  = (const float*)d_in[11];
    const float* gS   = (const float*)d_in[12];
    const float* bS   = (const float*)d_in[13];
    const float* WQs  = (const float*)d_in[14];
    const float* WKs  = (const float*)d_in[15];
    const float* cheb = (const float*)d_in[16];
    const float* adj  = (const float*)d_in[17];
    const float* mask = (const float*)d_in[18];
    const float* th   = (const float*)d_in[19];
    const float* w3   = (const float*)d_in[20];
    const float* b3   = (const float*)d_in[21];
    const float* w5   = (const float*)d_in[22];
    const float* b5   = (const float*)d_in[23];
    const float* w7   = (const float*)d_in[24];
    const float* b7   = (const float*)d_in[25];
    const float* rcw  = (const float*)d_in[26];
    const float* rcb  = (const float*)d_in[27];
    const float* fmw  = (const float*)d_in[28];
    const float* fmb  = (const float*)d_in[29];
    const float* gf   = (const float*)d_in[30];
    const float* bf   = (const float*)d_in[31];

    float* out   = (float*)d_out;
    float* reOut = out + (size_t)Bq * Nn * 32 * Tt;   // re_At follows main output

    cudaFuncSetAttribute(k7a_gtu, cudaFuncAttributeMaxDynamicSharedMemorySize, K7_FLOATS * 4);
    cudaFuncSetAttribute(k4_semx, cudaFuncAttributeMaxDynamicSharedMemorySize, K4_SMEM);

    k0_am    <<<3072, 256>>>(adj, mask);
    k0x_tr   <<<Bq * 8, 256>>>(x);
    k1_tln   <<<Bq * Tt, 256>>>(peT, gT, bT);
    k2a_qkv  <<<Bq * 32, 288>>>(WQt, WKt, WVt);
    k2b_attn <<<Bq, 288>>>(resA, reOut);
    k3_tat   <<<Bq * Tt, 256>>>(fct);
    k4_semx  <<<Bq * Nn / 32, 128, K4_SMEM>>>(pcw, pcb, peS, gS, bS);
    k5_qk    <<<Bq * Nn / 64, 256>>>(WQs, WKs);
    k6_spatial<<<Bq * 3 * 32, 256>>>(cheb);
    k7a_gtu  <<<(Bq * Nn / 32) * 4, 256, K7_FLOATS * 4>>>(th, w3, b3, w5, b5, w7, b7, fmw, fmb);
    k7b_final<<<Bq * Nn, 384>>>(x, rcw, rcb, gf, bf, out);
}

// round 14
// speedup vs baseline: 1.1511x; 1.0365x over previous
#include <cuda_runtime.h>

// ---------------- constants ----------------
constexpr int Bq = 16, Nn = 1024, Tt = 12;
constexpr float EPS = 1e-5f;
constexpr float ISQ32 = 0.17677669529663689f; // 1/sqrt(32)

// ---------------- scratch (device globals; allocation is forbidden) ----------------
__device__ __align__(16) float g_TEmx[Bq * Tt * Nn];
__device__ __align__(16) float g_ctx [Bq * Tt * 96];
__device__ __align__(16) float g_TAT [Bq * Tt * Nn];
__device__ __align__(16) float g_SEmx[Bq * Nn * 512];
__device__ __align__(16) float g_Qs  [Bq * 3 * Nn * 32];
__device__ __align__(16) float g_Ks  [Bq * 3 * Nn * 32];
__device__ __align__(16) float g_rhs [Bq * 3 * Nn * Tt];
__device__ __align__(16) float g_tco [Bq * Nn * Tt * 32];
__device__ __align__(16) float g_am  [3 * Nn * Nn];
__device__ __align__(16) float g_xT  [Bq * Tt * Nn];
__device__ __align__(16) float g_qkvp[Bq * 32 * 288 * 12];

__device__ __forceinline__ float warpsum(float v) {
#pragma unroll
    for (int o = 16; o; o >>= 1) v += __shfl_xor_sync(0xffffffffu, v, o);
    return v;
}
__device__ __forceinline__ unsigned long long pack2(float lo, float hi) {
    unsigned long long r;
    asm("mov.b64 %0, {%1,%2};" : "=l"(r) : "f"(lo), "f"(hi));
    return r;
}
__device__ __forceinline__ void unpack2(unsigned long long v, float& lo, float& hi) {
    asm("mov.b64 {%0,%1}, %2;" : "=f"(lo), "=f"(hi) : "l"(v));
}
__device__ __forceinline__ void fma2(unsigned long long& d, unsigned long long a,
                                     unsigned long long b) {
    asm("fma.rn.f32x2 %0, %1, %2, %3;" : "=l"(d) : "l"(a), "l"(b), "l"(d));
}
__device__ __forceinline__ float tanh_ap(float x) {
    float y; asm("tanh.approx.f32 %0, %1;" : "=f"(y) : "f"(x)); return y;
}

// ============ K0: g_am[k,i,j] = adj[i,j] * mask[k,i,j] ============
__global__ void k0_am(const float* __restrict__ adj, const float* __restrict__ mask) {
    int i = blockIdx.x * 256 + threadIdx.x;          // over float4, total 786432
    const float4 a = ((const float4*)adj)[i & 0x3FFFF];
    const float4 m = ((const float4*)mask)[i];
    float4 r; r.x = a.x * m.x; r.y = a.y * m.y; r.z = a.z * m.z; r.w = a.w * m.w;
    ((float4*)g_am)[i] = r;
}

// ============ K0x: xT[b,t,n] = x[b,n,0,t] ============
__global__ void k0x_tr(const float* __restrict__ x) {
    __shared__ float sxt[128][13];
    int b = blockIdx.x >> 3, n0 = (blockIdx.x & 7) * 128;
    int tid = threadIdx.x;
    for (int i = tid; i < 384; i += 256) {
        int r = i / 3, q = i % 3;
        float4 f = *(const float4*)(x + ((b * Nn + n0 + r) * 12 + q * 4));
        sxt[r][q * 4] = f.x; sxt[r][q * 4 + 1] = f.y; sxt[r][q * 4 + 2] = f.z; sxt[r][q * 4 + 3] = f.w;
    }
    __syncthreads();
    for (int i = tid; i < 1536; i += 256) {
        int t = i >> 7, r = i & 127;
        g_xT[(b * 12 + t) * Nn + n0 + r] = sxt[r][t];
    }
}

// ============ K1: TEmx[b,t,n] = LN_n(xT[b,t,n] + peT[t,n]) * gT[n] + bT[n] ============
__global__ void k1_tln(const float* __restrict__ peT, const float* __restrict__ gT,
                       const float* __restrict__ bT) {
    int b = blockIdx.x / Tt, t = blockIdx.x % Tt;
    __shared__ float rb[20];
    int tid = threadIdx.x;
    float4 xv = *(const float4*)(g_xT + (b * 12 + t) * Nn + tid * 4);
    float4 pe = *(const float4*)(peT + t * Nn + tid * 4);
    float4 v; v.x = xv.x + pe.x; v.y = xv.y + pe.y; v.z = xv.z + pe.z; v.w = xv.w + pe.w;
    float s = v.x + v.y + v.z + v.w;
    float q = v.x * v.x + v.y * v.y + v.z * v.z + v.w * v.w;
    s = warpsum(s); q = warpsum(q);
    int w = tid >> 5, l = tid & 31;
    if (l == 0) { rb[w] = s; rb[w + 8] = q; }
    __syncthreads();
    if (tid == 0) {
        float S = 0.f, Q = 0.f;
        for (int i = 0; i < 8; i++) { S += rb[i]; Q += rb[i + 8]; }
        float mu = S * (1.f / Nn); float var = Q * (1.f / Nn) - mu * mu;
        rb[16] = mu; rb[17] = rsqrtf(var + EPS);
    }
    __syncthreads();
    float mu = rb[16], rs = rb[17];
    float4 g = *(const float4*)(gT + tid * 4);
    float4 be = *(const float4*)(bT + tid * 4);
    float4 o;
    o.x = (v.x - mu) * rs * g.x + be.x; o.y = (v.y - mu) * rs * g.y + be.y;
    o.z = (v.z - mu) * rs * g.z + be.z; o.w = (v.w - mu) * rs * g.w + be.w;
    *(float4*)(g_TEmx + (b * 12 + t) * Nn + tid * 4) = o;
}

// ============ K2a: partial QKV sums over 32-n chunks (grid 16*32) ============
__global__ void k2a_qkv(const float* __restrict__ WQ, const float* __restrict__ WK,
                        const float* __restrict__ WV) {
    int blk = blockIdx.x, b = blk >> 5, ch = blk & 31;
    int tid = threadIdx.x;                 // 288
    __shared__ float srow[12][32];
    float acc[12];
#pragma unroll
    for (int t = 0; t < 12; t++) acc[t] = 0.f;
    const float* W = (tid < 96) ? WQ : (tid < 192) ? WK : WV;
    int col = tid % 96;
    int n0 = ch * 32;
    if (tid < 288) {
        int t = tid >> 5, nn = tid & 31;
        if (t < 12) srow[t][nn] = g_TEmx[(b * 12 + t) * Nn + n0 + nn];
    }
    for (int i = tid + 288; i < 384; i += 288) {
        int t = i >> 5, nn = i & 31;
        srow[t][nn] = g_TEmx[(b * 12 + t) * Nn + n0 + nn];
    }
    __syncthreads();
    for (int nn = 0; nn < 32; nn++) {
        float w = W[(n0 + nn) * 96 + col];
#pragma unroll
        for (int t = 0; t < 12; t++) acc[t] += srow[t][nn] * w;
    }
    float* op = g_qkvp + ((size_t)blk * 288 + tid) * 12;
#pragma unroll
    for (int t = 0; t < 12; t++) op[t] = acc[t];
}

// ============ K2b: reduce partials + temporal MHA (writes re_At, ctx) ============
__global__ void k2b_attn(const float* __restrict__ resA, float* __restrict__ reOut) {
    int b = blockIdx.x, tid = threadIdx.x;   // 288 threads
    __shared__ float sM[3][3][12][33];
    __shared__ float sS[3][12][12];
    float acc[12];
#pragma unroll
    for (int t = 0; t < 12; t++) acc[t] = 0.f;
#pragma unroll 8
    for (int ch = 0; ch < 32; ch++) {
        const float4* pp = (const float4*)(g_qkvp + ((size_t)(b * 32 + ch) * 288 + tid) * 12);
        float4 p0 = pp[0], p1 = pp[1], p2 = pp[2];
        acc[0] += p0.x; acc[1] += p0.y; acc[2] += p0.z; acc[3] += p0.w;
        acc[4] += p1.x; acc[5] += p1.y; acc[6] += p1.z; acc[7] += p1.w;
        acc[8] += p2.x; acc[9] += p2.y; acc[10] += p2.z; acc[11] += p2.w;
    }
    int col = tid % 96;
    {
        int m = tid / 96, h = col >> 5, d = col & 31;
#pragma unroll
        for (int t = 0; t < 12; t++) sM[m][h][t][d] = acc[t];
    }
    __syncthreads();
    for (int i = tid; i < 432; i += 288) {
        int h = i / 144, rem = i % 144, q = rem / 12, kk = rem % 12;
        float s = 0.f;
#pragma unroll
        for (int d = 0; d < 32; d++) s += sM[0][h][q][d] * sM[1][h][kk][d];
        s = s * ISQ32 + resA[((b * 3 + h) * 12 + q) * 12 + kk];
        sS[h][q][kk] = s;
        reOut[((b * 3 + h) * 12 + q) * 12 + kk] = s;
    }
    __syncthreads();
    if (tid < 36) {
        int h = tid / 12, q = tid % 12;
        float mx = -1e30f;
        for (int kk = 0; kk < 12; kk++) mx = fmaxf(mx, sS[h][q][kk]);
        float e[12]; float sum = 0.f;
        for (int kk = 0; kk < 12; kk++) { e[kk] = __expf(sS[h][q][kk] - mx); sum += e[kk]; }
        float inv = 1.f / sum;
        for (int kk = 0; kk < 12; kk++) sS[h][q][kk] = e[kk] * inv;
    }
    __syncthreads();
    {
        int h = tid / 96, rem = tid % 96, d = rem & 31, qg = rem >> 5;
#pragma unroll
        for (int j = 0; j < 4; j++) {
            int q = qg * 4 + j;
            float s = 0.f;
#pragma unroll
            for (int kk = 0; kk < 12; kk++) s += sS[h][q][kk] * sM[2][h][kk][d];
            g_ctx[(b * 12 + q) * 96 + h * 32 + d] = s;
        }
    }
}

// ============ K3: TAT = LN_n(ctx @ fc_t + TEmx), gamma=1 beta=0 — float4 path ============
__global__ void k3_tat(const float* __restrict__ fct) {
    int b = blockIdx.x / 12, t = blockIdx.x % 12;
    __shared__ float sc[96];
    __shared__ float rb[20];
    int tid = threadIdx.x;
    if (tid < 96) sc[tid] = g_ctx[(b * 12 + t) * 96 + tid];
    __syncthreads();
    float4 a = *(const float4*)(g_TEmx + (b * 12 + t) * Nn + tid * 4);
    const float4* fp = (const float4*)fct;
#pragma unroll 4
    for (int j = 0; j < 96; j++) {
        float c = sc[j];
        float4 f = fp[j * 256 + tid];
        a.x += c * f.x; a.y += c * f.y; a.z += c * f.z; a.w += c * f.w;
    }
    float s = a.x + a.y + a.z + a.w;
    float q = a.x * a.x + a.y * a.y + a.z * a.z + a.w * a.w;
    s = warpsum(s); q = warpsum(q);
    int w = tid >> 5, l = tid & 31;
    if (l == 0) { rb[w] = s; rb[w + 8] = q; }
    __syncthreads();
    if (tid == 0) {
        float S = 0.f, Q = 0.f;
        for (int i = 0; i < 8; i++) { S += rb[i]; Q += rb[i + 8]; }
        float mu = S * (1.f / Nn); float var = Q * (1.f / Nn) - mu * mu;
        rb[16] = mu; rb[17] = rsqrtf(var + EPS);
    }
    __syncthreads();
    float mu = rb[16], rs = rb[17];
    float4 o;
    o.x = (a.x - mu) * rs; o.y = (a.y - mu) * rs; o.z = (a.z - mu) * rs; o.w = (a.w - mu) * rs;
    *(float4*)(g_TAT + (b * 12 + t) * Nn + tid * 4) = o;
}

// ============ K4: SEmx = LN_d(pre_conv(TAT) + peS) — 32-row tiles, weights in regs ============
constexpr int K4_SMEM = (32 * 512 + 32 * 13) * 4;   // sV + sTAT
__global__ __launch_bounds__(128, 3)
void k4_semx(const float* __restrict__ pcw, const float* __restrict__ pcb,
             const float* __restrict__ peS, const float* __restrict__ gS,
             const float* __restrict__ bS) {
    extern __shared__ float s4[];
    float* sV   = s4;            // [32][512]
    float* sTAT = s4 + 32 * 512; // [32][13]
    int tid = threadIdx.x;
    int row0 = blockIdx.x * 32;
    int b = row0 >> 10, n0 = row0 & 1023;
    int d0 = tid * 4;
    float w[12][4];
#pragma unroll
    for (int di = 0; di < 4; di++) {
        const float4* pw = (const float4*)(pcw + (d0 + di) * 12);
        float4 a = pw[0], bb = pw[1], c = pw[2];
        w[0][di] = a.x;  w[1][di] = a.y;  w[2][di] = a.z;  w[3][di] = a.w;
        w[4][di] = bb.x; w[5][di] = bb.y; w[6][di] = bb.z; w[7][di] = bb.w;
        w[8][di] = c.x;  w[9][di] = c.y;  w[10][di] = c.z; w[11][di] = c.w;
    }
    float4 bias = *(const float4*)(pcb + d0);
    for (int i = tid; i < 12 * 32; i += 128) {
        int t = i >> 5, r = i & 31;
        sTAT[r * 13 + t] = g_TAT[(b * 12 + t) * Nn + n0 + r];
    }
    __syncthreads();
    for (int r = 0; r < 32; r++) {
        float4 pe = *(const float4*)(peS + (n0 + r) * 512 + d0);
        float v0 = bias.x + pe.x, v1 = bias.y + pe.y, v2 = bias.z + pe.z, v3 = bias.w + pe.w;
#pragma unroll
        for (int t = 0; t < 12; t++) {
            float tv = sTAT[r * 13 + t];
            v0 += tv * w[t][0]; v1 += tv * w[t][1]; v2 += tv * w[t][2]; v3 += tv * w[t][3];
        }
        float4 vv; vv.x = v0; vv.y = v1; vv.z = v2; vv.w = v3;
        *(float4*)(sV + r * 512 + d0) = vv;
    }
    __syncthreads();
    int warp = tid >> 5, lane = tid & 31;
    float gsr[16], bsr[16];
#pragma unroll
    for (int i = 0; i < 16; i++) { gsr[i] = gS[lane + 32 * i]; bsr[i] = bS[lane + 32 * i]; }
    for (int r = warp; r < 32; r += 4) {
        float s = 0.f, q = 0.f; float v[16];
#pragma unroll
        for (int i = 0; i < 16; i++) {
            float a = sV[r * 512 + lane + 32 * i];
            v[i] = a; s += a; q += a * a;
        }
        s = warpsum(s); q = warpsum(q);
        float mu = s * (1.f / 512.f), var = q * (1.f / 512.f) - mu * mu, rs = rsqrtf(var + EPS);
        float* outp = g_SEmx + (size_t)(row0 + r) * 512;
#pragma unroll
        for (int i = 0; i < 16; i++)
            outp[lane + 32 * i] = (v[i] - mu) * rs * gsr[i] + bsr[i];
    }
}

// ============ K5: (16384,512) @ (512,192) -> Qs(pre-scaled)|Ks — f32x2 ============
__global__ void k5_qk(const float* __restrict__ WQs, const float* __restrict__ WKs) {
    __shared__ float sA[16 * 66];                 // stride 66 for 8B-aligned u64 loads
    __shared__ float sB2[16 * 6 * 33 * 2];        // [kk][v][tt] duplicated (b,b) u64
    int tid = threadIdx.x, tx = tid & 31, ty = tid >> 5;
    int m0 = blockIdx.x * 64;
    unsigned long long acc2[4][6];
#pragma unroll
    for (int u = 0; u < 4; u++)
#pragma unroll
        for (int v = 0; v < 6; v++) acc2[u][v] = pack2(0.f, 0.f);
    for (int k0 = 0; k0 < 512; k0 += 16) {
        __syncthreads();
        {
            int rowl = tid >> 2, kq = (tid & 3) * 4;
            const float4 f = *(const float4*)(g_SEmx + (size_t)(m0 + rowl) * 512 + k0 + kq);
            sA[kq * 66 + rowl] = f.x; sA[(kq + 1) * 66 + rowl] = f.y;
            sA[(kq + 2) * 66 + rowl] = f.z; sA[(kq + 3) * 66 + rowl] = f.w;
        }
        for (int i = tid; i < 16 * 192; i += 256) {
            int kk = i / 192, c = i % 192;
            float v = (c < 96) ? WQs[(k0 + kk) * 96 + c] : WKs[(k0 + kk) * 96 + c - 96];
            int idx = 2 * ((kk * 6 + (c % 6)) * 33 + (c / 6));
            sB2[idx] = v; sB2[idx + 1] = v;
        }
        __syncthreads();
#pragma unroll
        for (int kk = 0; kk < 16; kk++) {
            unsigned long long a2[4], b2[6];
#pragma unroll
            for (int u = 0; u < 4; u++)
                a2[u] = *(const unsigned long long*)(sA + kk * 66 + ty * 8 + 2 * u);
#pragma unroll
            for (int v = 0; v < 6; v++)
                b2[v] = *(const unsigned long long*)(sB2 + 2 * ((kk * 6 + v) * 33 + tx));
#pragma unroll
            for (int u = 0; u < 4; u++)
#pragma unroll
                for (int v = 0; v < 6; v++) fma2(acc2[u][v], a2[u], b2[v]);
        }
    }
    for (int u = 0; u < 4; u++)
        for (int v = 0; v < 6; v++) {
            float lo, hi; unpack2(acc2[u][v], lo, hi);
            int c = tx * 6 + v;
#pragma unroll
            for (int h = 0; h < 2; h++) {
                int m = m0 + ty * 8 + 2 * u + h;
                float val = h ? hi : lo;
                int b = m >> 10, n = m & 1023;
                if (c < 96) g_Qs[((b * 3 + (c >> 5)) * Nn + n) * 32 + (c & 31)] = val * ISQ32;
                else { int cc = c - 96; g_Ks[((b * 3 + (cc >> 5)) * Nn + n) * 32 + (cc & 31)] = val; }
            }
        }
}

// ============ K6: fused spatial scores + softmax(over i) + Cheb contraction — f32x2 ============
// 64-j tiles, thread (jS, rbk) handles j ∈ {jS, jS+32}: kv/xp loads amortized over 2 j.
// Scorer-side accumulation (R11 structure); final reduction reuses staging smem (union).
__global__ void k6_spatial(const float* __restrict__ cheb) {
    int bk = blockIdx.x >> 4, jt = blockIdx.x & 15;
    int b = bk / 3, k = bk % 3;
    int j0 = jt * 64;
    __shared__ __align__(16) float sU[7168];      // union: sK|sQ|sx2 (5120) vs sRed (7168)
    float* sK = sU;                                // [64*34]
    float* sQ = sU + 2176;                         // [64*34]
    float2* sx2 = (float2*)(sU + 4352);            // [64*6]
    int tid = threadIdx.x;
    int jS = tid & 31, rbk = tid >> 5;
    for (int i = tid; i < 2048; i += 256) {
        int j = i >> 5, d = i & 31;
        sK[j * 34 + d] = g_Ks[((b * 3 + k) * Nn + j0 + j) * 32 + d];
    }
    unsigned long long acc0[6], acc1[6];
#pragma unroll
    for (int tp = 0; tp < 6; tp++) { acc0[tp] = pack2(0.f, 0.f); acc1[tp] = pack2(0.f, 0.f); }
    float den0 = 0.f, den1 = 0.f;
    int gj0 = j0 + jS, gj1 = j0 + jS + 32;
    __syncthreads();
    for (int i0 = 0; i0 < Nn; i0 += 64) {
        for (int i = tid; i < 2048; i += 256) {
            int r = i >> 5, d = i & 31;
            sQ[r * 34 + d] = g_Qs[((b * 3 + k) * Nn + i0 + r) * 32 + d];
        }
        for (int i = tid; i < 384; i += 256) {
            int tp = i >> 6, r = i & 63;
            sx2[r * 6 + tp] = make_float2(g_xT[(b * 12 + tp) * Nn + i0 + r],
                                          g_xT[(b * 12 + tp + 6) * Nn + i0 + r]);
        }
        __syncthreads();
        {   // scores for 8 rows x 2 j (packed over d-pairs)
            unsigned long long a0[8], a1[8];
#pragma unroll
            for (int r = 0; r < 8; r++) { a0[r] = pack2(0.f, 0.f); a1[r] = pack2(0.f, 0.f); }
            const float* qb = sQ + (rbk * 8) * 34;
#pragma unroll
            for (int d2 = 0; d2 < 16; d2++) {
                unsigned long long kv0 = *(const unsigned long long*)(sK + jS * 34 + 2 * d2);
                unsigned long long kv1 = *(const unsigned long long*)(sK + (jS + 32) * 34 + 2 * d2);
#pragma unroll
                for (int r = 0; r < 8; r++) {
                    unsigned long long qv = *(const unsigned long long*)(qb + r * 34 + 2 * d2);
                    fma2(a0[r], qv, kv0);
                    fma2(a1[r], qv, kv1);
                }
            }
            // exp + cheb weight + direct accumulation over this thread's 8 rows, both j
#pragma unroll
            for (int r = 0; r < 8; r++) {
                int gi = i0 + rbk * 8 + r;
                const float* amr = g_am + (size_t)(k * Nn + gi) * Nn;
                const float* chr = cheb + (size_t)(k * Nn + gi) * Nn;
                const unsigned long long* xp =
                    (const unsigned long long*)(sx2 + (rbk * 8 + r) * 6);
                float lo, hi;
                unpack2(a0[r], lo, hi);
                float e0 = __expf(lo + hi + amr[gj0]);
                den0 += e0;
                float w0 = e0 * chr[gj0];
                unpack2(a1[r], lo, hi);
                float e1 = __expf(lo + hi + amr[gj1]);
                den1 += e1;
                float w1 = e1 * chr[gj1];
                unsigned long long w02 = pack2(w0, w0);
                unsigned long long w12 = pack2(w1, w1);
#pragma unroll
                for (int tp = 0; tp < 6; tp++) {
                    unsigned long long xv = xp[tp];
                    fma2(acc0[tp], w02, xv);
                    fma2(acc1[tp], w12, xv);
                }
            }
        }
        __syncthreads();
    }
    // cross-rbk reduction (once per block); reuse sU as sRed[8][64][14]
    float* sRed = sU;
    {
        float* row0 = sRed + (rbk * 64 + jS) * 14;
        float* row1 = sRed + (rbk * 64 + jS + 32) * 14;
#pragma unroll
        for (int tp = 0; tp < 6; tp++) {
            float lo, hi;
            unpack2(acc0[tp], lo, hi);
            row0[tp] = lo; row0[tp + 6] = hi;
            unpack2(acc1[tp], lo, hi);
            row1[tp] = lo; row1[tp + 6] = hi;
        }
        row0[12] = den0;
        row1[12] = den1;
    }
    __syncthreads();
    for (int idx = tid; idx < 768; idx += 256) {
        int t = idx >> 6, j = idx & 63;
        float s = 0.f, d2 = 0.f;
#pragma unroll
        for (int g = 0; g < 8; g++) {
            const float* row = sRed + (g * 64 + j) * 14;
            s += row[t]; d2 += row[12];
        }
        g_rhs[((b * 3 + k) * Nn + j0 + j) * 12 + t] = s / d2;
    }
}

// ============ K7a: Theta-combine + GTU(3/5/7) + fcmy + inner relu -> g_tco ============
constexpr int OFF_W = 0, OFF_X = 8256, OFF_R = 20544, OFF_FW = 21696,
              OFF_TH = 21984, OFF_FB = 22080, K7_FLOATS = 22092;
__global__ __launch_bounds__(256, 2)
void k7a_gtu(const float* __restrict__ th,
             const float* __restrict__ w3, const float* __restrict__ b3,
             const float* __restrict__ w5, const float* __restrict__ b5,
             const float* __restrict__ w7, const float* __restrict__ b7,
             const float* __restrict__ fw, const float* __restrict__ fb) {
    extern __shared__ float sm[];
    int tid = threadIdx.x;
    int og  = blockIdx.x & 3;
    int rt0 = (blockIdx.x >> 2) * 32;
    for (int pi = tid; pi < 8 * 32 * 15; pi += 256) {
        int p = pi / 480, rem = pi % 480, c = rem / 15, j = rem % 15;
        int ot = og * 8 + p;
        float wt, ws;
        if (j < 3)      { wt = w3[(ot * 32 + c) * 3 + j];       ws = w3[((ot + 32) * 32 + c) * 3 + j]; }
        else if (j < 8) { wt = w5[(ot * 32 + c) * 5 + (j - 3)]; ws = w5[((ot + 32) * 32 + c) * 5 + (j - 3)]; }
        else            { wt = w7[(ot * 32 + c) * 7 + (j - 8)]; ws = w7[((ot + 32) * 32 + c) * 7 + (j - 8)]; }
        int off = OFF_W + p * 1032 + c * 32 + 2 * j;
        sm[off] = wt; sm[off + 1] = ws;
    }
    for (int pi = tid; pi < 144; pi += 256) {
        int j = pi / 6, tp = pi % 6;
        sm[OFF_FW + pi * 2]     = fw[j * 12 + tp];
        sm[OFF_FW + pi * 2 + 1] = fw[j * 12 + tp + 6];
    }
    if (tid < 96) sm[OFF_TH + tid] = th[tid];
    if (tid < 6) { sm[OFF_FB + tid * 2] = fb[tid]; sm[OFF_FB + tid * 2 + 1] = fb[tid + 6]; }
    for (int i = tid; i < 1152; i += 256) {
        int k = i / 384, rem = i % 384;
        int row = rt0 + rem / 12;
        int b = row >> 10, n = row & 1023;
        sm[OFF_R + i] = g_rhs[((b * 3 + k) * Nn + n) * 12 + rem % 12];
    }
    __syncthreads();
    for (int i = tid; i < 12288; i += 256) {
        int c = i / 384, rem = i % 384;
        float v = sm[OFF_R + rem] * sm[OFF_TH + c] + sm[OFF_R + 384 + rem] * sm[OFF_TH + 32 + c]
                + sm[OFF_R + 768 + rem] * sm[OFF_TH + 64 + c];
        sm[OFF_X + i] = fmaxf(v, 0.f);
    }
    __syncthreads();
    int p = tid & 7, r = tid >> 3;
    unsigned long long A3[10], A5[8], A7[6];
    {
        int ot = og * 8 + p;
        unsigned long long v3 = pack2(b3[ot], b3[32 + ot]);
        unsigned long long v5 = pack2(b5[ot], b5[32 + ot]);
        unsigned long long v7 = pack2(b7[ot], b7[32 + ot]);
#pragma unroll
        for (int i = 0; i < 10; i++) A3[i] = v3;
#pragma unroll
        for (int i = 0; i < 8; i++)  A5[i] = v5;
#pragma unroll
        for (int i = 0; i < 6; i++)  A7[i] = v7;
    }
    const float* xb = sm + OFF_X + r * 12;
    const unsigned long long* wp =
        (const unsigned long long*)(sm + OFF_W + p * 1032);
    for (int c = 0; c < 32; c++) {
        float4 x0 = *(const float4*)(xb + c * 384);
        float4 x1 = *(const float4*)(xb + c * 384 + 4);
        float4 x2 = *(const float4*)(xb + c * 384 + 8);
        unsigned long long xp[12];
        xp[0] = pack2(x0.x, x0.x); xp[1] = pack2(x0.y, x0.y); xp[2] = pack2(x0.z, x0.z);
        xp[3] = pack2(x0.w, x0.w); xp[4] = pack2(x1.x, x1.x); xp[5] = pack2(x1.y, x1.y);
        xp[6] = pack2(x1.z, x1.z); xp[7] = pack2(x1.w, x1.w); xp[8] = pack2(x2.x, x2.x);
        xp[9] = pack2(x2.y, x2.y); xp[10] = pack2(x2.z, x2.z); xp[11] = pack2(x2.w, x2.w);
        const unsigned long long* wc = wp + c * 16;
        unsigned long long wv[15];
#pragma unroll
        for (int j = 0; j < 15; j++) wv[j] = wc[j];
#pragma unroll
        for (int j = 0; j < 3; j++)
#pragma unroll
            for (int t = 0; t < 10; t++) fma2(A3[t], wv[j], xp[t + j]);
#pragma unroll
        for (int j = 0; j < 5; j++)
#pragma unroll
            for (int t = 0; t < 8; t++) fma2(A5[t], wv[3 + j], xp[t + j]);
#pragma unroll
        for (int j = 0; j < 7; j++)
#pragma unroll
            for (int t = 0; t < 6; t++) fma2(A7[t], wv[8 + j], xp[t + j]);
    }
    unsigned long long g2[24];
#pragma unroll
    for (int t = 0; t < 10; t++) {
        float at, as; unpack2(A3[t], at, as);
        float g = tanh_ap(at) * __fdividef(1.f, 1.f + __expf(-as));
        g2[t] = pack2(g, g);
    }
#pragma unroll
    for (int t = 0; t < 8; t++) {
        float at, as; unpack2(A5[t], at, as);
        float g = tanh_ap(at) * __fdividef(1.f, 1.f + __expf(-as));
        g2[10 + t] = pack2(g, g);
    }
#pragma unroll
    for (int t = 0; t < 6; t++) {
        float at, as; unpack2(A7[t], at, as);
        float g = tanh_ap(at) * __fdividef(1.f, 1.f + __expf(-as));
        g2[18 + t] = pack2(g, g);
    }
    int row = rt0 + r, oc = og * 8 + p;
    const unsigned long long* fwp = (const unsigned long long*)(sm + OFF_FW);
#pragma unroll
    for (int tp = 0; tp < 6; tp++) {
        unsigned long long acc = *(const unsigned long long*)(sm + OFF_FB + tp * 2);
#pragma unroll
        for (int j = 0; j < 24; j++) fma2(acc, g2[j], fwp[j * 6 + tp]);
        float lo, hi; unpack2(acc, lo, hi);
        g_tco[(row * 12 + tp) * 32 + oc]       = fmaxf(lo, 0.f);
        g_tco[(row * 12 + tp + 6) * 32 + oc]   = fmaxf(hi, 0.f);
    }
}

// ============ K7b: residual 1x1 conv + relu + channel LayerNorm -> out ============
__global__ void k7b_final(const float* __restrict__ xin, const float* __restrict__ rw,
                          const float* __restrict__ rb, const float* __restrict__ gf,
                          const float* __restrict__ bf, float* __restrict__ out) {
    __shared__ float sT[32 * 13];
    int bn = blockIdx.x;
    int t = threadIdx.x >> 5, c = threadIdx.x & 31;
    float xv = xin[bn * 12 + t];
    float v = fmaxf(xv * rw[c] + rb[c] + g_tco[(bn * 12 + t) * 32 + c], 0.f);
    float mu = warpsum(v) * (1.f / 32.f);
    float q  = warpsum(v * v) * (1.f / 32.f);
    float rs = rsqrtf(q - mu * mu + EPS);
    sT[c * 13 + t] = (v - mu) * rs * gf[c] + bf[c];
    __syncthreads();
    int cc = threadIdx.x / 12, tt2 = threadIdx.x % 12;
    out[bn * 384 + threadIdx.x] = sT[cc * 13 + tt2];
}

// ============================ launch ============================
extern "C" void kernel_launch(void* const* d_in, const int* in_sizes, int n_in,
                              void* d_out, int out_size) {
    const float* x    = (const float*)d_in[0];
    const float* resA = (const float*)d_in[1];
    const float* peT  = (const float*)d_in[2];
    const float* gT   = (const float*)d_in[3];
    const float* bT   = (const float*)d_in[4];
    const float* WQt  = (const float*)d_in[5];
    const float* WKt  = (const float*)d_in[6];
    const float* WVt  = (const float*)d_in[7];
    const float* fct  = (const float*)d_in[8];
    const float* pcw  = (const float*)d_in[9];
    const float* pcb  = (const float*)d_in[10];
    const float* peS  = (const float*)d_in[11];
    const float* gS   = (const float*)d_in[12];
    const float* bS   = (const float*)d_in[13];
    const float* WQs  = (const float*)d_in[14];
    const float* WKs  = (const float*)d_in[15];
    const float* cheb = (const float*)d_in[16];
    const float* adj  = (const float*)d_in[17];
    const float* mask = (const float*)d_in[18];
    const float* th   = (const float*)d_in[19];
    const float* w3   = (const float*)d_in[20];
    const float* b3   = (const float*)d_in[21];
    const float* w5   = (const float*)d_in[22];
    const float* b5   = (const float*)d_in[23];
    const float* w7   = (const float*)d_in[24];
    const float* b7   = (const float*)d_in[25];
    const float* rcw  = (const float*)d_in[26];
    const float* rcb  = (const float*)d_in[27];
    const float* fmw  = (const float*)d_in[28];
    const float* fmb  = (const float*)d_in[29];
    const float* gf   = (const float*)d_in[30];
    const float* bf   = (const float*)d_in[31];

    float* out   = (float*)d_out;
    float* reOut = out + (size_t)Bq * Nn * 32 * Tt;   // re_At follows main output

    cudaFuncSetAttribute(k7a_gtu, cudaFuncAttributeMaxDynamicSharedMemorySize, K7_FLOATS * 4);
    cudaFuncSetAttribute(k4_semx, cudaFuncAttributeMaxDynamicSharedMemorySize, K4_SMEM);

    k0_am    <<<3072, 256>>>(adj, mask);
    k0x_tr   <<<Bq * 8, 256>>>(x);
    k1_tln   <<<Bq * Tt, 256>>>(peT, gT, bT);
    k2a_qkv  <<<Bq * 32, 288>>>(WQt, WKt, WVt);
    k2b_attn <<<Bq, 288>>>(resA, reOut);
    k3_tat   <<<Bq * Tt, 256>>>(fct);
    k4_semx  <<<Bq * Nn / 32, 128, K4_SMEM>>>(pcw, pcb, peS, gS, bS);
    k5_qk    <<<Bq * Nn / 64, 256>>>(WQs, WKs);
    k6_spatial<<<Bq * 3 * 16, 256>>>(cheb);
    k7a_gtu  <<<(Bq * Nn / 32) * 4, 256, K7_FLOATS * 4>>>(th, w3, b3, w5, b5, w7, b7, fmw, fmb);
    k7b_final<<<Bq * Nn, 384>>>(x, rcw, rcb, gf, bf, out);
}